// round 1
// baseline (speedup 1.0000x reference)
#include <cuda_runtime.h>
#include <cuda_bf16.h>

#define NN 50000
#define EE 800000
#define IN_CH 256
#define HEADS 4
#define OUT_CH 32
#define HC 128            // HEADS*OUT_CH
#define NEG_SLOPE 0.2f
#define EPSV 1e-16f

#define SCAN_T 1024
#define NB1 ((NN + SCAN_T - 1) / SCAN_T)   // 49

// ---------------- scratch (device globals; no allocation) ----------------
__device__ float g_h[(size_t)NN * HC];         // projected features [N,128]
__device__ float g_asrc[NN * HEADS];
__device__ float g_adst[NN * HEADS];
__device__ float g_alpha[(size_t)EE * HEADS];  // exp(leakyrelu(alpha)) per edge
__device__ float g_sum[NN * HEADS];            // segment sum of exp
__device__ int   g_deg[NN];
__device__ int   g_offsets[NN + 1];
__device__ int   g_cursor[NN];
__device__ int   g_blocksums[NB1];
__device__ int   g_csr_src[EE];
__device__ float4 g_csr_w[EE];                 // per-edge per-head normalized weight

// ---------------- 0: zero per-launch state ----------------
__global__ void init_kernel() {
    int i = blockIdx.x * blockDim.x + threadIdx.x;
    if (i < NN * HEADS) g_sum[i] = 0.f;
    if (i < NN) g_deg[i] = 0;
}

// ---------------- 1: GEMM h = x @ W2  (W2[k][h*32+c] = weight[h][k][c]) ----------------
__global__ __launch_bounds__(256, 2) void gemm_kernel(const float* __restrict__ x,
                                                      const float* __restrict__ w) {
    __shared__ float As[8][128];
    __shared__ float Bs[8][128];
    const int tid = threadIdx.x;
    const int block_m = blockIdx.x * 128;
    const int rowb = (tid >> 4) * 8;   // 0..120
    const int colb = (tid & 15) * 8;   // 0..120

    // loader indices
    const int lm = tid >> 1;           // 0..127 (x row within tile)
    const int lk = (tid & 1) * 4;      // 0 or 4
    const int wk = tid >> 5;           // 0..7  (k within tile)
    const int wn0 = (tid & 31) * 4;    // 0..124
    const int whead = wn0 >> 5;
    const int wc = wn0 & 31;

    float acc[8][8];
#pragma unroll
    for (int i = 0; i < 8; i++)
#pragma unroll
        for (int j = 0; j < 8; j++) acc[i][j] = 0.f;

    for (int k0 = 0; k0 < IN_CH; k0 += 8) {
        int gm = block_m + lm;
        float4 xv = make_float4(0.f, 0.f, 0.f, 0.f);
        if (gm < NN) xv = *(const float4*)(x + (size_t)gm * IN_CH + k0 + lk);
        As[lk + 0][lm] = xv.x;
        As[lk + 1][lm] = xv.y;
        As[lk + 2][lm] = xv.z;
        As[lk + 3][lm] = xv.w;
        float4 wv = *(const float4*)(w + whead * (IN_CH * OUT_CH) + (k0 + wk) * OUT_CH + wc);
        *(float4*)&Bs[wk][wn0] = wv;
        __syncthreads();
#pragma unroll
        for (int k = 0; k < 8; k++) {
            float a[8], b[8];
            *(float4*)(a)     = *(float4*)&As[k][rowb];
            *(float4*)(a + 4) = *(float4*)&As[k][rowb + 4];
            *(float4*)(b)     = *(float4*)&Bs[k][colb];
            *(float4*)(b + 4) = *(float4*)&Bs[k][colb + 4];
#pragma unroll
            for (int i = 0; i < 8; i++)
#pragma unroll
                for (int j = 0; j < 8; j++) acc[i][j] += a[i] * b[j];
        }
        __syncthreads();
    }
#pragma unroll
    for (int i = 0; i < 8; i++) {
        int gm = block_m + rowb + i;
        if (gm < NN) {
            float4 v0 = make_float4(acc[i][0], acc[i][1], acc[i][2], acc[i][3]);
            float4 v1 = make_float4(acc[i][4], acc[i][5], acc[i][6], acc[i][7]);
            *(float4*)(g_h + (size_t)gm * HC + colb)     = v0;
            *(float4*)(g_h + (size_t)gm * HC + colb + 4) = v1;
        }
    }
}

// ---------------- 2: per-(node,head) attention dots ----------------
__global__ void attdot_kernel(const float* __restrict__ att) {
    int idx = blockIdx.x * blockDim.x + threadIdx.x;
    if (idx >= NN * HEADS) return;
    int n = idx >> 2, hh = idx & 3;
    const float* hp = g_h + (size_t)n * HC + hh * OUT_CH;
    const float* a1p = att + hh * (2 * OUT_CH);
    const float* a2p = a1p + OUT_CH;
    float s = 0.f, d = 0.f;
#pragma unroll
    for (int c = 0; c < OUT_CH; c += 4) {
        float4 v  = *(const float4*)(hp + c);
        float4 a1 = *(const float4*)(a1p + c);
        float4 a2 = *(const float4*)(a2p + c);
        s += v.x * a1.x + v.y * a1.y + v.z * a1.z + v.w * a1.w;
        d += v.x * a2.x + v.y * a2.y + v.z * a2.z + v.w * a2.w;
    }
    g_asrc[idx] = s;
    g_adst[idx] = d;
}

// ---------------- 3: edge pass: exp(leakyrelu), segment sums, degrees ----------------
__global__ void edge_kernel(const int* __restrict__ ei) {
    int e = blockIdx.x * blockDim.x + threadIdx.x;
    if (e >= EE) return;
    int src = ei[e];
    int dst = ei[EE + e];
    float4 as = *(const float4*)(g_asrc + src * 4);
    float4 ad = *(const float4*)(g_adst + dst * 4);
    float al0 = as.x + ad.x, al1 = as.y + ad.y, al2 = as.z + ad.z, al3 = as.w + ad.w;
    al0 = al0 > 0.f ? al0 : NEG_SLOPE * al0;
    al1 = al1 > 0.f ? al1 : NEG_SLOPE * al1;
    al2 = al2 > 0.f ? al2 : NEG_SLOPE * al2;
    al3 = al3 > 0.f ? al3 : NEG_SLOPE * al3;
    float4 ex = make_float4(__expf(al0), __expf(al1), __expf(al2), __expf(al3));
    *(float4*)(g_alpha + (size_t)e * 4) = ex;
    atomicAdd(&g_sum[dst * 4 + 0], ex.x);
    atomicAdd(&g_sum[dst * 4 + 1], ex.y);
    atomicAdd(&g_sum[dst * 4 + 2], ex.z);
    atomicAdd(&g_sum[dst * 4 + 3], ex.w);
    atomicAdd(&g_deg[dst], 1);
}

// ---------------- 4: scan degrees -> CSR offsets ----------------
__global__ void scan1_kernel() {
    __shared__ int sm[SCAN_T];
    int b = blockIdx.x, t = threadIdx.x;
    int i = b * SCAN_T + t;
    int v = (i < NN) ? g_deg[i] : 0;
    sm[t] = v;
    __syncthreads();
    for (int off = 1; off < SCAN_T; off <<= 1) {
        int add = (t >= off) ? sm[t - off] : 0;
        __syncthreads();
        sm[t] += add;
        __syncthreads();
    }
    if (i < NN) g_offsets[i] = sm[t] - v;  // exclusive within block
    if (t == SCAN_T - 1) g_blocksums[b] = sm[t];
}

__global__ void scan2_kernel() {
    if (threadIdx.x == 0 && blockIdx.x == 0) {
        int acc = 0;
        for (int b = 0; b < NB1; b++) {
            int v = g_blocksums[b];
            g_blocksums[b] = acc;
            acc += v;
        }
    }
}

__global__ void scan3_kernel() {
    int i = blockIdx.x * blockDim.x + threadIdx.x;
    if (i < NN) {
        int o = g_offsets[i] + g_blocksums[i >> 10];
        g_offsets[i] = o;
        g_cursor[i] = o;
    }
    if (i == 0) g_offsets[NN] = EE;
}

// ---------------- 5: CSR fill with normalized weights ----------------
__global__ void csrfill_kernel(const int* __restrict__ ei) {
    int e = blockIdx.x * blockDim.x + threadIdx.x;
    if (e >= EE) return;
    int src = ei[e];
    int dst = ei[EE + e];
    float4 ae = *(const float4*)(g_alpha + (size_t)e * 4);
    float4 s = *(const float4*)(g_sum + dst * 4);
    int pos = atomicAdd(&g_cursor[dst], 1);
    g_csr_src[pos] = src;
    float4 w;
    w.x = ae.x / (s.x + EPSV);
    w.y = ae.y / (s.y + EPSV);
    w.z = ae.z / (s.z + EPSV);
    w.w = ae.w / (s.w + EPSV);
    g_csr_w[pos] = w;
}

// ---------------- 6: gather-aggregate per node ----------------
__global__ __launch_bounds__(128) void aggregate_kernel(float* __restrict__ out,
                                                        const float* __restrict__ bias) {
    int n = blockIdx.x;
    int t = threadIdx.x;
    int head = t >> 5;
    int beg = g_offsets[n];
    int end = g_offsets[n + 1];
    const float* wbase = (const float*)g_csr_w;
    float acc = 0.f;
    int i = beg;
    for (; i + 1 < end; i += 2) {
        int s0 = g_csr_src[i];
        int s1 = g_csr_src[i + 1];
        float w0 = wbase[(size_t)i * 4 + head];
        float w1 = wbase[(size_t)(i + 1) * 4 + head];
        float v0 = g_h[(size_t)s0 * HC + t];
        float v1 = g_h[(size_t)s1 * HC + t];
        acc += v0 * w0 + v1 * w1;
    }
    if (i < end) {
        int s0 = g_csr_src[i];
        float w0 = wbase[(size_t)i * 4 + head];
        acc += g_h[(size_t)s0 * HC + t] * w0;
    }
    out[(size_t)n * HC + t] = acc + __ldg(bias + t);
}

// ---------------- launcher ----------------
extern "C" void kernel_launch(void* const* d_in, const int* in_sizes, int n_in,
                              void* d_out, int out_size) {
    const float* x   = (const float*)d_in[0];
    const int* ei    = (const int*)d_in[1];
    const float* w   = (const float*)d_in[2];
    const float* att = (const float*)d_in[3];
    const float* bias= (const float*)d_in[4];
    float* out = (float*)d_out;

    init_kernel<<<(NN * HEADS + 255) / 256, 256>>>();
    gemm_kernel<<<(NN + 127) / 128, 256>>>(x, w);
    attdot_kernel<<<(NN * HEADS + 255) / 256, 256>>>(att);
    edge_kernel<<<(EE + 255) / 256, 256>>>(ei);
    scan1_kernel<<<NB1, SCAN_T>>>();
    scan2_kernel<<<1, 32>>>();
    scan3_kernel<<<(NN + 255) / 256, 256>>>();
    csrfill_kernel<<<(EE + 255) / 256, 256>>>(ei);
    aggregate_kernel<<<NN, 128>>>(out, bias);
}

// round 3
// speedup vs baseline: 1.4518x; 1.4518x over previous
#include <cuda_runtime.h>
#include <cuda_bf16.h>
#include <cstdint>

#define NN 50000
#define EE 800000
#define IN_CH 256
#define HEADS 4
#define OUT_CH 32
#define HC 128
#define NEG_SLOPE 0.2f
#define EPSV 1e-16f

#define SCAN_T 1024
#define NB1 ((NN + SCAN_T - 1) / SCAN_T)

#define BM 128
#define BN 128
#define BK 32
#define APAD 4
#define BPAD 8

// ---------------- scratch ----------------
__device__ float g_h[(size_t)NN * HC];
__device__ float g_bk[IN_CH * HC];             // W as [k][n], tf32-rounded
__device__ float g_asrc[NN * HEADS];
__device__ float g_adst[NN * HEADS];
__device__ float g_alpha[(size_t)EE * HEADS];  // exp(leakyrelu(alpha))
__device__ int   g_deg[NN];
__device__ int   g_offsets[NN + 1];
__device__ int   g_cursor[NN];
__device__ int   g_blocksums[NB1];
__device__ int   g_csr_src[EE];
__device__ float4 g_csr_w[EE];                 // unnormalized exp weights (CSR order)

__device__ __forceinline__ float tf32r(float x) {
    uint32_t b;
    asm("cvt.rna.tf32.f32 %0, %1;" : "=r"(b) : "f"(x));
    return __uint_as_float(b);
}

// ---------------- 0: init ----------------
__global__ void init_kernel() {
    int i = blockIdx.x * blockDim.x + threadIdx.x;
    if (i < NN) g_deg[i] = 0;
}

// ---------------- 0b: W -> [k][n] tf32 table ----------------
__global__ void wprep_kernel(const float* __restrict__ w) {
    int idx = blockIdx.x * blockDim.x + threadIdx.x;  // k*128 + n
    if (idx >= IN_CH * HC) return;
    int k = idx >> 7, n = idx & 127;
    g_bk[idx] = tf32r(w[(n >> 5) * (IN_CH * OUT_CH) + k * OUT_CH + (n & 31)]);
}

// ---------------- 1: GEMM h = x @ W  via mma.sync tf32 ----------------
__global__ __launch_bounds__(256, 2) void gemm_mma_kernel(const float* __restrict__ x) {
    __shared__ float As[BM][BK + APAD];
    __shared__ float Bs[BK][BN + BPAD];
    const int tid = threadIdx.x;
    const int lane = tid & 31;
    const int wid = tid >> 5;
    const int wm = wid >> 1;      // 0..3 (M direction)
    const int wn = wid & 1;       // 0..1 (N direction)
    const int block_m = blockIdx.x * BM;
    const int g = lane >> 2;      // groupID 0..7
    const int tg = lane & 3;      // threadID_in_group 0..3

    float c[2][8][4];
#pragma unroll
    for (int mt = 0; mt < 2; mt++)
#pragma unroll
        for (int nt = 0; nt < 8; nt++)
#pragma unroll
            for (int j = 0; j < 4; j++) c[mt][nt][j] = 0.f;

    for (int k0 = 0; k0 < IN_CH; k0 += BK) {
        // load A tile 128x32 (tf32-rounded)
#pragma unroll
        for (int i = 0; i < 4; i++) {
            int idx = tid + i * 256;
            int r = idx >> 3, c4 = idx & 7;
            int gm = block_m + r;
            float4 v = make_float4(0.f, 0.f, 0.f, 0.f);
            if (gm < NN) v = *(const float4*)(x + (size_t)gm * IN_CH + k0 + c4 * 4);
            v.x = tf32r(v.x); v.y = tf32r(v.y); v.z = tf32r(v.z); v.w = tf32r(v.w);
            *(float4*)&As[r][c4 * 4] = v;
        }
        // load B tile 32x128 (already tf32)
#pragma unroll
        for (int i = 0; i < 4; i++) {
            int idx = tid + i * 256;
            int r = idx >> 5, c4 = idx & 31;
            *(float4*)&Bs[r][c4 * 4] = *(const float4*)(g_bk + (k0 + r) * HC + c4 * 4);
        }
        __syncthreads();

#pragma unroll
        for (int kk = 0; kk < BK; kk += 8) {
            uint32_t a[2][4];
#pragma unroll
            for (int mt = 0; mt < 2; mt++) {
                int ar = wm * 32 + mt * 16 + g;
                a[mt][0] = __float_as_uint(As[ar][kk + tg]);
                a[mt][1] = __float_as_uint(As[ar + 8][kk + tg]);
                a[mt][2] = __float_as_uint(As[ar][kk + tg + 4]);
                a[mt][3] = __float_as_uint(As[ar + 8][kk + tg + 4]);
            }
#pragma unroll
            for (int nt = 0; nt < 8; nt++) {
                int bc = wn * 64 + nt * 8 + g;
                uint32_t b0 = __float_as_uint(Bs[kk + tg][bc]);
                uint32_t b1 = __float_as_uint(Bs[kk + tg + 4][bc]);
#pragma unroll
                for (int mt = 0; mt < 2; mt++) {
                    asm volatile(
                        "mma.sync.aligned.m16n8k8.row.col.f32.tf32.tf32.f32 "
                        "{%0,%1,%2,%3}, {%4,%5,%6,%7}, {%8,%9}, {%0,%1,%2,%3};"
                        : "+f"(c[mt][nt][0]), "+f"(c[mt][nt][1]),
                          "+f"(c[mt][nt][2]), "+f"(c[mt][nt][3])
                        : "r"(a[mt][0]), "r"(a[mt][1]), "r"(a[mt][2]), "r"(a[mt][3]),
                          "r"(b0), "r"(b1));
                }
            }
        }
        __syncthreads();
    }

    // epilogue: direct float2 stores
#pragma unroll
    for (int mt = 0; mt < 2; mt++) {
#pragma unroll
        for (int nt = 0; nt < 8; nt++) {
            int col = wn * 64 + nt * 8 + tg * 2;
            int r0 = block_m + wm * 32 + mt * 16 + g;
            if (r0 < NN)
                *(float2*)(g_h + (size_t)r0 * HC + col) = make_float2(c[mt][nt][0], c[mt][nt][1]);
            int r1 = r0 + 8;
            if (r1 < NN)
                *(float2*)(g_h + (size_t)r1 * HC + col) = make_float2(c[mt][nt][2], c[mt][nt][3]);
        }
    }
}

// ---------------- 2: per-(node,head) attention dots ----------------
__global__ void attdot_kernel(const float* __restrict__ att) {
    int idx = blockIdx.x * blockDim.x + threadIdx.x;
    if (idx >= NN * HEADS) return;
    int n = idx >> 2, hh = idx & 3;
    const float* hp = g_h + (size_t)n * HC + hh * OUT_CH;
    const float* a1p = att + hh * (2 * OUT_CH);
    const float* a2p = a1p + OUT_CH;
    float s = 0.f, d = 0.f;
#pragma unroll
    for (int cc = 0; cc < OUT_CH; cc += 4) {
        float4 v  = *(const float4*)(hp + cc);
        float4 a1 = *(const float4*)(a1p + cc);
        float4 a2 = *(const float4*)(a2p + cc);
        s += v.x * a1.x + v.y * a1.y + v.z * a1.z + v.w * a1.w;
        d += v.x * a2.x + v.y * a2.y + v.z * a2.z + v.w * a2.w;
    }
    g_asrc[idx] = s;
    g_adst[idx] = d;
}

// ---------------- 3: edge pass: exp(leakyrelu) + degree ----------------
__global__ void edge_kernel(const int* __restrict__ ei) {
    int e = blockIdx.x * blockDim.x + threadIdx.x;
    if (e >= EE) return;
    int src = ei[e];
    int dst = ei[EE + e];
    float4 as = *(const float4*)(g_asrc + src * 4);
    float4 ad = *(const float4*)(g_adst + dst * 4);
    float al0 = as.x + ad.x, al1 = as.y + ad.y, al2 = as.z + ad.z, al3 = as.w + ad.w;
    al0 = al0 > 0.f ? al0 : NEG_SLOPE * al0;
    al1 = al1 > 0.f ? al1 : NEG_SLOPE * al1;
    al2 = al2 > 0.f ? al2 : NEG_SLOPE * al2;
    al3 = al3 > 0.f ? al3 : NEG_SLOPE * al3;
    float4 ex = make_float4(__expf(al0), __expf(al1), __expf(al2), __expf(al3));
    *(float4*)(g_alpha + (size_t)e * 4) = ex;
    atomicAdd(&g_deg[dst], 1);
}

// ---------------- 4: scan degrees -> CSR offsets ----------------
__global__ void scan1_kernel() {
    __shared__ int sm[SCAN_T];
    int b = blockIdx.x, t = threadIdx.x;
    int i = b * SCAN_T + t;
    int v = (i < NN) ? g_deg[i] : 0;
    sm[t] = v;
    __syncthreads();
    for (int off = 1; off < SCAN_T; off <<= 1) {
        int add = (t >= off) ? sm[t - off] : 0;
        __syncthreads();
        sm[t] += add;
        __syncthreads();
    }
    if (i < NN) g_offsets[i] = sm[t] - v;
    if (t == SCAN_T - 1) g_blocksums[b] = sm[t];
}

__global__ void scan2_kernel() {
    if (threadIdx.x == 0 && blockIdx.x == 0) {
        int acc = 0;
        for (int b = 0; b < NB1; b++) {
            int v = g_blocksums[b];
            g_blocksums[b] = acc;
            acc += v;
        }
    }
}

__global__ void scan3_kernel() {
    int i = blockIdx.x * blockDim.x + threadIdx.x;
    if (i < NN) {
        int o = g_offsets[i] + g_blocksums[i >> 10];
        g_offsets[i] = o;
        g_cursor[i] = o;
    }
    if (i == 0) g_offsets[NN] = EE;
}

// ---------------- 5: CSR fill (unnormalized weights) ----------------
__global__ void csrfill_kernel(const int* __restrict__ ei) {
    int e = blockIdx.x * blockDim.x + threadIdx.x;
    if (e >= EE) return;
    int src = ei[e];
    int dst = ei[EE + e];
    float4 ae = *(const float4*)(g_alpha + (size_t)e * 4);
    int pos = atomicAdd(&g_cursor[dst], 1);
    g_csr_src[pos] = src;
    g_csr_w[pos] = ae;
}

// ---------------- 6: gather-aggregate (normalize in epilogue) ----------------
__global__ __launch_bounds__(128) void aggregate_kernel(float* __restrict__ out,
                                                        const float* __restrict__ bias) {
    int n = blockIdx.x;
    int t = threadIdx.x;
    int head = t >> 5;
    int beg = g_offsets[n];
    int end = g_offsets[n + 1];
    const float* wbase = (const float*)g_csr_w;
    float acc = 0.f, sw = 0.f;
    int i = beg;
    for (; i + 1 < end; i += 2) {
        int s0 = g_csr_src[i];
        int s1 = g_csr_src[i + 1];
        float w0 = wbase[(size_t)i * 4 + head];
        float w1 = wbase[(size_t)(i + 1) * 4 + head];
        float v0 = g_h[(size_t)s0 * HC + t];
        float v1 = g_h[(size_t)s1 * HC + t];
        acc += v0 * w0 + v1 * w1;
        sw += w0 + w1;
    }
    if (i < end) {
        int s0 = g_csr_src[i];
        float w0 = wbase[(size_t)i * 4 + head];
        acc += g_h[(size_t)s0 * HC + t] * w0;
        sw += w0;
    }
    out[(size_t)n * HC + t] = acc / (sw + EPSV) + __ldg(bias + t);
}

// ---------------- launcher ----------------
extern "C" void kernel_launch(void* const* d_in, const int* in_sizes, int n_in,
                              void* d_out, int out_size) {
    const float* x    = (const float*)d_in[0];
    const int* ei     = (const int*)d_in[1];
    const float* w    = (const float*)d_in[2];
    const float* att  = (const float*)d_in[3];
    const float* bias = (const float*)d_in[4];
    float* out = (float*)d_out;

    init_kernel<<<(NN + 255) / 256, 256>>>();
    wprep_kernel<<<(IN_CH * HC + 255) / 256, 256>>>(w);
    gemm_mma_kernel<<<(NN + BM - 1) / BM, 256>>>(x);
    attdot_kernel<<<(NN * HEADS + 255) / 256, 256>>>(att);
    edge_kernel<<<(EE + 255) / 256, 256>>>(ei);
    scan1_kernel<<<NB1, SCAN_T>>>();
    scan2_kernel<<<1, 32>>>();
    scan3_kernel<<<(NN + 255) / 256, 256>>>();
    csrfill_kernel<<<(EE + 255) / 256, 256>>>(ei);
    aggregate_kernel<<<NN, 128>>>(out, bias);
}

// round 4
// speedup vs baseline: 1.5091x; 1.0394x over previous
#include <cuda_runtime.h>
#include <cuda_bf16.h>
#include <cstdint>

#define NN 50000
#define EE 800000
#define IN_CH 256
#define HEADS 4
#define OUT_CH 32
#define HC 128
#define NEG_SLOPE 0.2f
#define EPSV 1e-16f

#define SCAN_T 1024
#define NB1 ((NN + SCAN_T - 1) / SCAN_T)

#define BM 128
#define BN 128
#define BK 32
#define APAD 4
#define BPAD 8

// ---------------- scratch ----------------
__device__ float g_h[(size_t)NN * HC];
__device__ float g_bk[IN_CH * HC];             // W as [k][n], tf32-rounded
__device__ float g_asrc[NN * HEADS];
__device__ float g_adst[NN * HEADS];
__device__ int   g_deg[NN];
__device__ int   g_offsets[NN + 1];
__device__ int   g_cursor[NN];
__device__ int   g_blocksums[NB1];
__device__ int   g_csr_src[EE];
__device__ float4 g_csr_w[EE];                 // unnormalized exp weights (CSR order)

__device__ __forceinline__ float tf32r(float x) {
    uint32_t b;
    asm("cvt.rna.tf32.f32 %0, %1;" : "=r"(b) : "f"(x));
    return __uint_as_float(b);
}

// ---------------- 0: init ----------------
__global__ void init_kernel() {
    int i = blockIdx.x * blockDim.x + threadIdx.x;
    if (i < NN) g_deg[i] = 0;
}

// ---------------- 0b: W -> [k][n] tf32 table ----------------
__global__ void wprep_kernel(const float* __restrict__ w) {
    int idx = blockIdx.x * blockDim.x + threadIdx.x;  // k*128 + n
    if (idx >= IN_CH * HC) return;
    int k = idx >> 7, n = idx & 127;
    g_bk[idx] = tf32r(w[(n >> 5) * (IN_CH * OUT_CH) + k * OUT_CH + (n & 31)]);
}

// ---------------- 1: GEMM h = x @ W  via mma.sync tf32 ----------------
__global__ __launch_bounds__(256, 2) void gemm_mma_kernel(const float* __restrict__ x) {
    __shared__ float As[BM][BK + APAD];
    __shared__ float Bs[BK][BN + BPAD];
    const int tid = threadIdx.x;
    const int lane = tid & 31;
    const int wid = tid >> 5;
    const int wm = wid >> 1;
    const int wn = wid & 1;
    const int block_m = blockIdx.x * BM;
    const int g = lane >> 2;
    const int tg = lane & 3;

    float c[2][8][4];
#pragma unroll
    for (int mt = 0; mt < 2; mt++)
#pragma unroll
        for (int nt = 0; nt < 8; nt++)
#pragma unroll
            for (int j = 0; j < 4; j++) c[mt][nt][j] = 0.f;

    for (int k0 = 0; k0 < IN_CH; k0 += BK) {
#pragma unroll
        for (int i = 0; i < 4; i++) {
            int idx = tid + i * 256;
            int r = idx >> 3, c4 = idx & 7;
            int gm = block_m + r;
            float4 v = make_float4(0.f, 0.f, 0.f, 0.f);
            if (gm < NN) v = *(const float4*)(x + (size_t)gm * IN_CH + k0 + c4 * 4);
            v.x = tf32r(v.x); v.y = tf32r(v.y); v.z = tf32r(v.z); v.w = tf32r(v.w);
            *(float4*)&As[r][c4 * 4] = v;
        }
#pragma unroll
        for (int i = 0; i < 4; i++) {
            int idx = tid + i * 256;
            int r = idx >> 5, c4 = idx & 31;
            *(float4*)&Bs[r][c4 * 4] = *(const float4*)(g_bk + (k0 + r) * HC + c4 * 4);
        }
        __syncthreads();

#pragma unroll
        for (int kk = 0; kk < BK; kk += 8) {
            uint32_t a[2][4];
#pragma unroll
            for (int mt = 0; mt < 2; mt++) {
                int ar = wm * 32 + mt * 16 + g;
                a[mt][0] = __float_as_uint(As[ar][kk + tg]);
                a[mt][1] = __float_as_uint(As[ar + 8][kk + tg]);
                a[mt][2] = __float_as_uint(As[ar][kk + tg + 4]);
                a[mt][3] = __float_as_uint(As[ar + 8][kk + tg + 4]);
            }
#pragma unroll
            for (int nt = 0; nt < 8; nt++) {
                int bc = wn * 64 + nt * 8 + g;
                uint32_t b0 = __float_as_uint(Bs[kk + tg][bc]);
                uint32_t b1 = __float_as_uint(Bs[kk + tg + 4][bc]);
#pragma unroll
                for (int mt = 0; mt < 2; mt++) {
                    asm volatile(
                        "mma.sync.aligned.m16n8k8.row.col.f32.tf32.tf32.f32 "
                        "{%0,%1,%2,%3}, {%4,%5,%6,%7}, {%8,%9}, {%0,%1,%2,%3};"
                        : "+f"(c[mt][nt][0]), "+f"(c[mt][nt][1]),
                          "+f"(c[mt][nt][2]), "+f"(c[mt][nt][3])
                        : "r"(a[mt][0]), "r"(a[mt][1]), "r"(a[mt][2]), "r"(a[mt][3]),
                          "r"(b0), "r"(b1));
                }
            }
        }
        __syncthreads();
    }

#pragma unroll
    for (int mt = 0; mt < 2; mt++) {
#pragma unroll
        for (int nt = 0; nt < 8; nt++) {
            int col = wn * 64 + nt * 8 + tg * 2;
            int r0 = block_m + wm * 32 + mt * 16 + g;
            if (r0 < NN)
                *(float2*)(g_h + (size_t)r0 * HC + col) = make_float2(c[mt][nt][0], c[mt][nt][1]);
            int r1 = r0 + 8;
            if (r1 < NN)
                *(float2*)(g_h + (size_t)r1 * HC + col) = make_float2(c[mt][nt][2], c[mt][nt][3]);
        }
    }
}

// ---------------- 2: attention dots, warp-per-node (coalesced) ----------------
__global__ __launch_bounds__(256) void attdot_kernel(const float* __restrict__ att) {
    __shared__ float s_a1[HEADS][OUT_CH];
    __shared__ float s_a2[HEADS][OUT_CH];
    int tid = threadIdx.x;
    if (tid < HEADS * OUT_CH) {
        int hh = tid >> 5, cc = tid & 31;
        s_a1[hh][cc] = att[hh * (2 * OUT_CH) + cc];
        s_a2[hh][cc] = att[hh * (2 * OUT_CH) + OUT_CH + cc];
    }
    __syncthreads();
    int lane = tid & 31;
    int warp = tid >> 5;
    int n = blockIdx.x * 8 + warp;
    if (n >= NN) return;
    int head = lane >> 3;
    int c0 = (lane & 7) * 4;  // 0..28 within head
    float4 v = *(const float4*)(g_h + (size_t)n * HC + lane * 4);
    float4 a1 = *(const float4*)&s_a1[head][c0];
    float4 a2 = *(const float4*)&s_a2[head][c0];
    float s = v.x * a1.x + v.y * a1.y + v.z * a1.z + v.w * a1.w;
    float d = v.x * a2.x + v.y * a2.y + v.z * a2.z + v.w * a2.w;
#pragma unroll
    for (int off = 4; off > 0; off >>= 1) {
        s += __shfl_xor_sync(0xFFFFFFFF, s, off);
        d += __shfl_xor_sync(0xFFFFFFFF, d, off);
    }
    if ((lane & 7) == 0) {
        g_asrc[n * 4 + head] = s;
        g_adst[n * 4 + head] = d;
    }
}

// ---------------- 3: degree count (dst only) ----------------
__global__ void deg_kernel(const int* __restrict__ ei) {
    int e = blockIdx.x * blockDim.x + threadIdx.x;
    if (e >= EE) return;
    atomicAdd(&g_deg[ei[EE + e]], 1);
}

// ---------------- 4: scan degrees -> CSR offsets ----------------
__global__ void scan1_kernel() {
    __shared__ int sm[SCAN_T];
    int b = blockIdx.x, t = threadIdx.x;
    int i = b * SCAN_T + t;
    int v = (i < NN) ? g_deg[i] : 0;
    sm[t] = v;
    __syncthreads();
    for (int off = 1; off < SCAN_T; off <<= 1) {
        int add = (t >= off) ? sm[t - off] : 0;
        __syncthreads();
        sm[t] += add;
        __syncthreads();
    }
    if (i < NN) g_offsets[i] = sm[t] - v;
    if (t == SCAN_T - 1) g_blocksums[b] = sm[t];
}

__global__ void scan2_kernel() {
    if (threadIdx.x == 0 && blockIdx.x == 0) {
        int acc = 0;
        for (int b = 0; b < NB1; b++) {
            int v = g_blocksums[b];
            g_blocksums[b] = acc;
            acc += v;
        }
    }
}

__global__ void scan3_kernel() {
    int i = blockIdx.x * blockDim.x + threadIdx.x;
    if (i < NN) {
        int o = g_offsets[i] + g_blocksums[i >> 10];
        g_offsets[i] = o;
        g_cursor[i] = o;
    }
    if (i == 0) g_offsets[NN] = EE;
}

// ---------------- 5: fused edge pass: exp(leakyrelu) -> CSR slot ----------------
__global__ void edgefill_kernel(const int* __restrict__ ei) {
    int e = blockIdx.x * blockDim.x + threadIdx.x;
    if (e >= EE) return;
    int src = ei[e];
    int dst = ei[EE + e];
    float4 as = *(const float4*)(g_asrc + src * 4);
    float4 ad = *(const float4*)(g_adst + dst * 4);
    float al0 = as.x + ad.x, al1 = as.y + ad.y, al2 = as.z + ad.z, al3 = as.w + ad.w;
    al0 = al0 > 0.f ? al0 : NEG_SLOPE * al0;
    al1 = al1 > 0.f ? al1 : NEG_SLOPE * al1;
    al2 = al2 > 0.f ? al2 : NEG_SLOPE * al2;
    al3 = al3 > 0.f ? al3 : NEG_SLOPE * al3;
    float4 ex = make_float4(__expf(al0), __expf(al1), __expf(al2), __expf(al3));
    int pos = atomicAdd(&g_cursor[dst], 1);
    g_csr_src[pos] = src;
    g_csr_w[pos] = ex;
}

// ---------------- 6: gather-aggregate (normalize in epilogue, 4x unroll) ----------------
__global__ __launch_bounds__(128) void aggregate_kernel(float* __restrict__ out,
                                                        const float* __restrict__ bias) {
    int n = blockIdx.x;
    int t = threadIdx.x;
    int head = t >> 5;
    int beg = g_offsets[n];
    int end = g_offsets[n + 1];
    const float* wbase = (const float*)g_csr_w;
    float acc = 0.f, sw = 0.f;
    int i = beg;
    for (; i + 3 < end; i += 4) {
        int s0 = g_csr_src[i];
        int s1 = g_csr_src[i + 1];
        int s2 = g_csr_src[i + 2];
        int s3 = g_csr_src[i + 3];
        float w0 = wbase[(size_t)i * 4 + head];
        float w1 = wbase[(size_t)(i + 1) * 4 + head];
        float w2 = wbase[(size_t)(i + 2) * 4 + head];
        float w3 = wbase[(size_t)(i + 3) * 4 + head];
        float v0 = g_h[(size_t)s0 * HC + t];
        float v1 = g_h[(size_t)s1 * HC + t];
        float v2 = g_h[(size_t)s2 * HC + t];
        float v3 = g_h[(size_t)s3 * HC + t];
        acc += v0 * w0 + v1 * w1 + v2 * w2 + v3 * w3;
        sw += w0 + w1 + w2 + w3;
    }
    for (; i < end; i++) {
        int s0 = g_csr_src[i];
        float w0 = wbase[(size_t)i * 4 + head];
        acc += g_h[(size_t)s0 * HC + t] * w0;
        sw += w0;
    }
    out[(size_t)n * HC + t] = acc / (sw + EPSV) + __ldg(bias + t);
}

// ---------------- launcher ----------------
extern "C" void kernel_launch(void* const* d_in, const int* in_sizes, int n_in,
                              void* d_out, int out_size) {
    const float* x    = (const float*)d_in[0];
    const int* ei     = (const int*)d_in[1];
    const float* w    = (const float*)d_in[2];
    const float* att  = (const float*)d_in[3];
    const float* bias = (const float*)d_in[4];
    float* out = (float*)d_out;

    init_kernel<<<(NN + 255) / 256, 256>>>();
    wprep_kernel<<<(IN_CH * HC + 255) / 256, 256>>>(w);
    gemm_mma_kernel<<<(NN + BM - 1) / BM, 256>>>(x);
    attdot_kernel<<<(NN + 7) / 8, 256>>>(att);
    deg_kernel<<<(EE + 255) / 256, 256>>>(ei);
    scan1_kernel<<<NB1, SCAN_T>>>();
    scan2_kernel<<<1, 32>>>();
    scan3_kernel<<<(NN + 255) / 256, 256>>>();
    edgefill_kernel<<<(EE + 255) / 256, 256>>>(ei);
    aggregate_kernel<<<NN, 128>>>(out, bias);
}

// round 8
// speedup vs baseline: 1.6145x; 1.0698x over previous
#include <cuda_runtime.h>
#include <cuda_bf16.h>
#include <cstdint>

#define NN 50000
#define EE 800000
#define IN_CH 256
#define HEADS 4
#define OUT_CH 32
#define HC 128
#define NEG_SLOPE 0.2f
#define EPSV 1e-16f

#define SCAN_T 1024
#define NB1 ((NN + SCAN_T - 1) / SCAN_T)

#define BM 128
#define BN 128
#define BK 32
#define APAD 4
#define BPAD 8

// ---------------- scratch ----------------
__device__ float g_h[(size_t)NN * HC];           // projected features, fp32
__device__ float g_bk[IN_CH * HC];               // W as [k][n], tf32-rounded
__device__ float g_asrc[NN * HEADS];
__device__ float g_adst[NN * HEADS];
__device__ int   g_deg[NN];
__device__ int   g_offsets[NN + 1];
__device__ int   g_cursor[NN];
__device__ int   g_blocksums[NB1];
__device__ int   g_csr_src[EE];
__device__ float4 g_csr_w[EE];                   // unnormalized exp weights (CSR order)

__device__ __forceinline__ float tf32r(float x) {
    uint32_t b;
    asm("cvt.rna.tf32.f32 %0, %1;" : "=r"(b) : "f"(x));
    return __uint_as_float(b);
}

// ---------------- 0: init ----------------
__global__ void init_kernel() {
    int i = blockIdx.x * blockDim.x + threadIdx.x;
    if (i < NN) g_deg[i] = 0;
}

// ---------------- 0b: W -> [k][n] tf32 table ----------------
__global__ void wprep_kernel(const float* __restrict__ w) {
    int idx = blockIdx.x * blockDim.x + threadIdx.x;  // k*128 + n
    if (idx >= IN_CH * HC) return;
    int k = idx >> 7, n = idx & 127;
    g_bk[idx] = tf32r(w[(n >> 5) * (IN_CH * OUT_CH) + k * OUT_CH + (n & 31)]);
}

// ---------------- 1: GEMM + fused attdot ----------------
__global__ __launch_bounds__(256, 2) void gemm_mma_kernel(const float* __restrict__ x,
                                                          const float* __restrict__ att) {
    __shared__ float As[BM][BK + APAD];
    __shared__ float Bs[BK][BN + BPAD];
    __shared__ float s_a1[HEADS][OUT_CH];
    __shared__ float s_a2[HEADS][OUT_CH];
    const int tid = threadIdx.x;
    const int lane = tid & 31;
    const int wid = tid >> 5;
    const int wm = wid >> 1;
    const int wn = wid & 1;
    const int block_m = blockIdx.x * BM;
    const int g = lane >> 2;
    const int tg = lane & 3;

    if (tid < HEADS * OUT_CH) {
        int hh = tid >> 5, cc = tid & 31;
        s_a1[hh][cc] = att[hh * (2 * OUT_CH) + cc];
        s_a2[hh][cc] = att[hh * (2 * OUT_CH) + OUT_CH + cc];
    }

    float c[2][8][4];
#pragma unroll
    for (int mt = 0; mt < 2; mt++)
#pragma unroll
        for (int nt = 0; nt < 8; nt++)
#pragma unroll
            for (int j = 0; j < 4; j++) c[mt][nt][j] = 0.f;

    // ---- initial tile 0 ----
    {
#pragma unroll
        for (int i = 0; i < 4; i++) {
            int idx = tid + i * 256;
            int r = idx >> 3, c4 = idx & 7;
            int gm = block_m + r;
            float4 v = make_float4(0.f, 0.f, 0.f, 0.f);
            if (gm < NN) v = *(const float4*)(x + (size_t)gm * IN_CH + c4 * 4);
            v.x = tf32r(v.x); v.y = tf32r(v.y); v.z = tf32r(v.z); v.w = tf32r(v.w);
            *(float4*)&As[r][c4 * 4] = v;
        }
#pragma unroll
        for (int i = 0; i < 4; i++) {
            int idx = tid + i * 256;
            int r = idx >> 5, c4 = idx & 31;
            *(float4*)&Bs[r][c4 * 4] = *(const float4*)(g_bk + r * HC + c4 * 4);
        }
    }
    __syncthreads();

    for (int k0 = 0; k0 < IN_CH; k0 += BK) {
        const bool has_next = (k0 + BK) < IN_CH;
        float4 pa[4], pb[4];
        if (has_next) {
#pragma unroll
            for (int i = 0; i < 4; i++) {
                int idx = tid + i * 256;
                int r = idx >> 3, c4 = idx & 7;
                int gm = block_m + r;
                pa[i] = make_float4(0.f, 0.f, 0.f, 0.f);
                if (gm < NN) pa[i] = *(const float4*)(x + (size_t)gm * IN_CH + k0 + BK + c4 * 4);
            }
#pragma unroll
            for (int i = 0; i < 4; i++) {
                int idx = tid + i * 256;
                int r = idx >> 5, c4 = idx & 31;
                pb[i] = *(const float4*)(g_bk + (k0 + BK + r) * HC + c4 * 4);
            }
        }

#pragma unroll
        for (int kk = 0; kk < BK; kk += 8) {
            uint32_t a[2][4];
#pragma unroll
            for (int mt = 0; mt < 2; mt++) {
                int ar = wm * 32 + mt * 16 + g;
                a[mt][0] = __float_as_uint(As[ar][kk + tg]);
                a[mt][1] = __float_as_uint(As[ar + 8][kk + tg]);
                a[mt][2] = __float_as_uint(As[ar][kk + tg + 4]);
                a[mt][3] = __float_as_uint(As[ar + 8][kk + tg + 4]);
            }
#pragma unroll
            for (int nt = 0; nt < 8; nt++) {
                int bc = wn * 64 + nt * 8 + g;
                uint32_t b0 = __float_as_uint(Bs[kk + tg][bc]);
                uint32_t b1 = __float_as_uint(Bs[kk + tg + 4][bc]);
#pragma unroll
                for (int mt = 0; mt < 2; mt++) {
                    asm volatile(
                        "mma.sync.aligned.m16n8k8.row.col.f32.tf32.tf32.f32 "
                        "{%0,%1,%2,%3}, {%4,%5,%6,%7}, {%8,%9}, {%0,%1,%2,%3};"
                        : "+f"(c[mt][nt][0]), "+f"(c[mt][nt][1]),
                          "+f"(c[mt][nt][2]), "+f"(c[mt][nt][3])
                        : "r"(a[mt][0]), "r"(a[mt][1]), "r"(a[mt][2]), "r"(a[mt][3]),
                          "r"(b0), "r"(b1));
                }
            }
        }
        __syncthreads();
        if (has_next) {
#pragma unroll
            for (int i = 0; i < 4; i++) {
                int idx = tid + i * 256;
                int r = idx >> 3, c4 = idx & 7;
                float4 v = pa[i];
                v.x = tf32r(v.x); v.y = tf32r(v.y); v.z = tf32r(v.z); v.w = tf32r(v.w);
                *(float4*)&As[r][c4 * 4] = v;
            }
#pragma unroll
            for (int i = 0; i < 4; i++) {
                int idx = tid + i * 256;
                int r = idx >> 5, c4 = idx & 31;
                *(float4*)&Bs[r][c4 * 4] = pb[i];
            }
            __syncthreads();
        }
    }

    // ---- epilogue: fp32 h store + fused attention dots ----
    float ps[2][2][2], pd[2][2][2];  // [mt][rowhalf][headLocal]
#pragma unroll
    for (int mt = 0; mt < 2; mt++)
#pragma unroll
        for (int rh = 0; rh < 2; rh++)
#pragma unroll
            for (int hl = 0; hl < 2; hl++) { ps[mt][rh][hl] = 0.f; pd[mt][rh][hl] = 0.f; }

#pragma unroll
    for (int mt = 0; mt < 2; mt++) {
#pragma unroll
        for (int nt = 0; nt < 8; nt++) {
            const int col = wn * 64 + nt * 8 + tg * 2;
            const int hl = nt >> 2;
            const int head = 2 * wn + hl;
            const int colh = (nt & 3) * 8 + tg * 2;
            const float a10 = s_a1[head][colh], a11 = s_a1[head][colh + 1];
            const float a20 = s_a2[head][colh], a21 = s_a2[head][colh + 1];
            const int r0 = block_m + wm * 32 + mt * 16 + g;
            const int r1 = r0 + 8;
            if (r0 < NN)
                *(float2*)(g_h + (size_t)r0 * HC + col) = make_float2(c[mt][nt][0], c[mt][nt][1]);
            if (r1 < NN)
                *(float2*)(g_h + (size_t)r1 * HC + col) = make_float2(c[mt][nt][2], c[mt][nt][3]);
            ps[mt][0][hl] += c[mt][nt][0] * a10 + c[mt][nt][1] * a11;
            ps[mt][1][hl] += c[mt][nt][2] * a10 + c[mt][nt][3] * a11;
            pd[mt][0][hl] += c[mt][nt][0] * a20 + c[mt][nt][1] * a21;
            pd[mt][1][hl] += c[mt][nt][2] * a20 + c[mt][nt][3] * a21;
        }
    }
    // reduce over the 4 lanes sharing a row-group (tg = lane bits 0..1)
#pragma unroll
    for (int off = 1; off <= 2; off <<= 1) {
#pragma unroll
        for (int mt = 0; mt < 2; mt++)
#pragma unroll
            for (int rh = 0; rh < 2; rh++)
#pragma unroll
                for (int hl = 0; hl < 2; hl++) {
                    ps[mt][rh][hl] += __shfl_xor_sync(0xFFFFFFFF, ps[mt][rh][hl], off);
                    pd[mt][rh][hl] += __shfl_xor_sync(0xFFFFFFFF, pd[mt][rh][hl], off);
                }
    }
    if (tg == 0) {
#pragma unroll
        for (int mt = 0; mt < 2; mt++)
#pragma unroll
            for (int rh = 0; rh < 2; rh++) {
                int row = block_m + wm * 32 + mt * 16 + g + rh * 8;
                if (row < NN) {
#pragma unroll
                    for (int hl = 0; hl < 2; hl++) {
                        g_asrc[row * 4 + 2 * wn + hl] = ps[mt][rh][hl];
                        g_adst[row * 4 + 2 * wn + hl] = pd[mt][rh][hl];
                    }
                }
            }
    }
}

// ---------------- 3: degree count (dst only) ----------------
__global__ void deg_kernel(const int* __restrict__ ei) {
    int e = blockIdx.x * blockDim.x + threadIdx.x;
    if (e >= EE) return;
    atomicAdd(&g_deg[ei[EE + e]], 1);
}

// ---------------- 4: scan degrees -> CSR offsets ----------------
__global__ void scan1_kernel() {
    __shared__ int sm[SCAN_T];
    int b = blockIdx.x, t = threadIdx.x;
    int i = b * SCAN_T + t;
    int v = (i < NN) ? g_deg[i] : 0;
    sm[t] = v;
    __syncthreads();
    for (int off = 1; off < SCAN_T; off <<= 1) {
        int add = (t >= off) ? sm[t - off] : 0;
        __syncthreads();
        sm[t] += add;
        __syncthreads();
    }
    if (i < NN) g_offsets[i] = sm[t] - v;
    if (t == SCAN_T - 1) g_blocksums[b] = sm[t];
}

__global__ void scan2_kernel() {
    if (threadIdx.x == 0 && blockIdx.x == 0) {
        int acc = 0;
        for (int b = 0; b < NB1; b++) {
            int v = g_blocksums[b];
            g_blocksums[b] = acc;
            acc += v;
        }
    }
}

__global__ void scan3_kernel() {
    int i = blockIdx.x * blockDim.x + threadIdx.x;
    if (i < NN) {
        int o = g_offsets[i] + g_blocksums[i >> 10];
        g_offsets[i] = o;
        g_cursor[i] = o;
    }
    if (i == 0) g_offsets[NN] = EE;
}

// ---------------- 5: fused edge pass: exp(leakyrelu) -> CSR slot ----------------
__global__ void edgefill_kernel(const int* __restrict__ ei) {
    int e = blockIdx.x * blockDim.x + threadIdx.x;
    if (e >= EE) return;
    int src = ei[e];
    int dst = ei[EE + e];
    float4 as = *(const float4*)(g_asrc + src * 4);
    float4 ad = *(const float4*)(g_adst + dst * 4);
    float al0 = as.x + ad.x, al1 = as.y + ad.y, al2 = as.z + ad.z, al3 = as.w + ad.w;
    al0 = al0 > 0.f ? al0 : NEG_SLOPE * al0;
    al1 = al1 > 0.f ? al1 : NEG_SLOPE * al1;
    al2 = al2 > 0.f ? al2 : NEG_SLOPE * al2;
    al3 = al3 > 0.f ? al3 : NEG_SLOPE * al3;
    float4 ex = make_float4(__expf(al0), __expf(al1), __expf(al2), __expf(al3));
    int pos = atomicAdd(&g_cursor[dst], 1);
    g_csr_src[pos] = src;
    g_csr_w[pos] = ex;
}

// ---------------- 6: gather-aggregate (normalize in epilogue, 4x unroll) ----------------
__global__ __launch_bounds__(128) void aggregate_kernel(float* __restrict__ out,
                                                        const float* __restrict__ bias) {
    int n = blockIdx.x;
    int t = threadIdx.x;
    int head = t >> 5;
    int beg = g_offsets[n];
    int end = g_offsets[n + 1];
    const float* wbase = (const float*)g_csr_w;
    float acc = 0.f, sw = 0.f;
    int i = beg;
    for (; i + 3 < end; i += 4) {
        int s0 = g_csr_src[i];
        int s1 = g_csr_src[i + 1];
        int s2 = g_csr_src[i + 2];
        int s3 = g_csr_src[i + 3];
        float w0 = wbase[(size_t)i * 4 + head];
        float w1 = wbase[(size_t)(i + 1) * 4 + head];
        float w2 = wbase[(size_t)(i + 2) * 4 + head];
        float w3 = wbase[(size_t)(i + 3) * 4 + head];
        float v0 = g_h[(size_t)s0 * HC + t];
        float v1 = g_h[(size_t)s1 * HC + t];
        float v2 = g_h[(size_t)s2 * HC + t];
        float v3 = g_h[(size_t)s3 * HC + t];
        acc += v0 * w0 + v1 * w1 + v2 * w2 + v3 * w3;
        sw += w0 + w1 + w2 + w3;
    }
    for (; i < end; i++) {
        int s0 = g_csr_src[i];
        float w0 = wbase[(size_t)i * 4 + head];
        acc += g_h[(size_t)s0 * HC + t] * w0;
        sw += w0;
    }
    out[(size_t)n * HC + t] = acc / (sw + EPSV) + __ldg(bias + t);
}

// ---------------- launcher ----------------
extern "C" void kernel_launch(void* const* d_in, const int* in_sizes, int n_in,
                              void* d_out, int out_size) {
    const float* x    = (const float*)d_in[0];
    const int* ei     = (const int*)d_in[1];
    const float* w    = (const float*)d_in[2];
    const float* att  = (const float*)d_in[3];
    const float* bias = (const float*)d_in[4];
    float* out = (float*)d_out;

    init_kernel<<<(NN + 255) / 256, 256>>>();
    wprep_kernel<<<(IN_CH * HC + 255) / 256, 256>>>(w);
    gemm_mma_kernel<<<(NN + BM - 1) / BM, 256>>>(x, att);
    deg_kernel<<<(EE + 255) / 256, 256>>>(ei);
    scan1_kernel<<<NB1, SCAN_T>>>();
    scan2_kernel<<<1, 32>>>();
    scan3_kernel<<<(NN + 255) / 256, 256>>>();
    edgefill_kernel<<<(EE + 255) / 256, 256>>>(ei);
    aggregate_kernel<<<NN, 128>>>(out, bias);
}